// round 9
// baseline (speedup 1.0000x reference)
#include <cuda_runtime.h>
#include <cuda_fp16.h>

#define DEV_INLINE __device__ __forceinline__

constexpr int NN   = 1024;
constexpr int EE   = 65536;
constexpr int E2   = EE + NN;      // edges + self loops
constexpr int W1O  = 512;          // H*256
constexpr int C1   = 256;
constexpr int W2O  = 128;          // H*64
constexpr int C2   = 64;

// ---------------- scratch (device globals) -------------
__device__ __half g_xph[2][NN * W1O];   // layer-1 projected features (fp16)
__device__ float  g_xp[2][NN * W2O];    // layer-2 projected features (fp32)
__device__ float  g_h1a[NN * W1O];      // layer-1 partial (rel 0, normalized)
__device__ float  g_h1b[NN * W1O];      // layer-1 partial (rel 1, normalized)
__device__ float  g_bb[W1O];            // b1_0+b1_1
__device__ float  g_cbias[1];           // sum((b2_0+b2_1)*wlin)
__device__ float  g_att[2][2 * 2 * NN * 2];  // [layer][rel][als/ald][node*2+head]
__device__ int    g_cnt4[4][2][NN];     // sharded edge counts
__device__ int    g_cur4[4][2][NN];     // sharded fill cursors
__device__ int    g_off[2][NN + 1];
__device__ int    g_srcs[2][E2];
__device__ float  g_s2[2][NN];          // per-relation score partials
__device__ int    g_flag;               // scan-done flag

// ---------------- packed f32x2 helpers ----------------
DEV_INLINE void fma2(unsigned long long& d, unsigned long long a, unsigned long long b) {
    asm("fma.rn.f32x2 %0, %1, %2, %0;" : "+l"(d) : "l"(a), "l"(b));
}
DEV_INLINE unsigned long long dup2(float v) {
    unsigned long long r;
    asm("mov.b64 %0, {%1, %1};" : "=l"(r) : "f"(v));
    return r;
}
DEV_INLINE float2 unpack2(unsigned long long v) {
    float2 f;
    asm("mov.b64 {%0, %1}, %2;" : "=f"(f.x), "=f"(f.y) : "l"(v));
    return f;
}

// =======================================================================
// FUSED: gemm1 (both relations, fp16 out, f32x2 math) + attn1 logits
//        + sharded edge count (+flag reset)
// =======================================================================
constexpr int G1_GEMM_BLOCKS  = (W1O / 64) * (NN / 128) * 2;   // 128
constexpr int G1_COUNT_BLOCKS = EE / 4 / 256;                  // 64

__global__ void __launch_bounds__(256)
k_gemm1_count(const float* __restrict__ A,
              const float* __restrict__ B0, const float* __restrict__ B1,
              __half* __restrict__ Ch0, __half* __restrict__ Ch1,
              const int* __restrict__ ei0, const int* __restrict__ ei1,
              const float* __restrict__ as0, const float* __restrict__ as1,
              const float* __restrict__ ad0, const float* __restrict__ ad1,
              float* __restrict__ att) {
    int bid = blockIdx.x;
    int t = threadIdx.x;

    if (bid >= G1_GEMM_BLOCKS) {
        if (bid == G1_GEMM_BLOCKS && t == 0) g_flag = 0;   // reset for scanfill
        int cid = bid - G1_GEMM_BLOCKS;
        int idx = cid * 256 + t;
        int4 d0 = ((const int4*)(ei0 + EE))[idx];
        int4 d1 = ((const int4*)(ei1 + EE))[idx];
        atomicAdd(&g_cnt4[0][0][d0.x], 1); atomicAdd(&g_cnt4[1][0][d0.y], 1);
        atomicAdd(&g_cnt4[2][0][d0.z], 1); atomicAdd(&g_cnt4[3][0][d0.w], 1);
        atomicAdd(&g_cnt4[0][1][d1.x], 1); atomicAdd(&g_cnt4[1][1][d1.y], 1);
        atomicAdd(&g_cnt4[2][1][d1.z], 1); atomicAdd(&g_cnt4[3][1][d1.w], 1);
        return;
    }

    constexpr int K = 256, Nc = W1O;
    __shared__ float smem[16 * 256 + 16 * 64];   // As_dup (16KB) + Bs (4KB)
    float* Asd = smem;             // [16][256] duplicated pairs
    float* Bs  = smem + 16 * 256;  // [16][64]

    int rel = bid >> 6;
    int r   = bid & 63;
    int bn  = (r & 7) * 64;
    int bm  = (r >> 3) * 128;
    const float* B = rel ? B1 : B0;
    __half*      Ch = rel ? Ch1 : Ch0;

    int tx = t & 15, ty = t >> 4;
    int am = t >> 2, ak = (t & 3) * 4;

    unsigned long long acc2[8][2];
    #pragma unroll
    for (int i = 0; i < 8; i++) { acc2[i][0] = 0ULL; acc2[i][1] = 0ULL; }

    float4 a_reg0 = *(const float4*)(A + (size_t)(bm + am) * K + ak);
    float4 a_reg1 = *(const float4*)(A + (size_t)(bm + am + 64) * K + ak);
    float4 b_reg  = *(const float4*)(B + (size_t)(t >> 4) * Nc + bn + (t & 15) * 4);

    for (int k0 = 0; k0 < K; k0 += 16) {
        {
            float a0[4] = {a_reg0.x, a_reg0.y, a_reg0.z, a_reg0.w};
            float a1[4] = {a_reg1.x, a_reg1.y, a_reg1.z, a_reg1.w};
            #pragma unroll
            for (int j = 0; j < 4; j++) {
                ((unsigned long long*)(Asd + (ak + j) * 256))[am]      = dup2(a0[j]);
                ((unsigned long long*)(Asd + (ak + j) * 256))[am + 64] = dup2(a1[j]);
            }
        }
        ((float4*)(Bs + (t >> 4) * 64))[t & 15] = b_reg;
        __syncthreads();

        if (k0 + 16 < K) {
            a_reg0 = *(const float4*)(A + (size_t)(bm + am) * K + k0 + 16 + ak);
            a_reg1 = *(const float4*)(A + (size_t)(bm + am + 64) * K + k0 + 16 + ak);
            b_reg  = *(const float4*)(B + (size_t)(k0 + 16 + (t >> 4)) * Nc + bn + (t & 15) * 4);
        }

        #pragma unroll
        for (int k = 0; k < 16; k++) {
            const unsigned long long* ad =
                (const unsigned long long*)(Asd + k * 256) + ty * 8;
            unsigned long long b01 = ((const unsigned long long*)(Bs + k * 64))[tx * 2];
            unsigned long long b23 = ((const unsigned long long*)(Bs + k * 64))[tx * 2 + 1];
            #pragma unroll
            for (int i = 0; i < 8; i++) {
                fma2(acc2[i][0], ad[i], b01);
                fma2(acc2[i][1], ad[i], b23);
            }
        }
        __syncthreads();
    }

    float4 acc[8];
    #pragma unroll
    for (int i = 0; i < 8; i++) {
        float2 p = unpack2(acc2[i][0]);
        float2 q = unpack2(acc2[i][1]);
        acc[i] = make_float4(p.x, p.y, q.x, q.y);
    }

    #pragma unroll
    for (int i = 0; i < 8; i++) {
        __half2 h01 = __floats2half2_rn(acc[i].x, acc[i].y);
        __half2 h23 = __floats2half2_rn(acc[i].z, acc[i].w);
        uint2 v;
        v.x = *reinterpret_cast<unsigned*>(&h01);
        v.y = *reinterpret_cast<unsigned*>(&h23);
        ((uint2*)(Ch + (size_t)(bm + ty * 8 + i) * Nc))[(bn >> 2) + tx] = v;
    }

    // fused attn1 logit partials
    const float* asrc = rel ? as1 : as0;
    const float* adst = rel ? ad1 : ad0;
    int h   = bn >> 8;
    int cin = (bn & 255) + tx * 4;
    float4 avs = *(const float4*)(asrc + h * C1 + cin);
    float4 avd = *(const float4*)(adst + h * C1 + cin);
    float* alsb = att + (rel * 2 + 0) * (NN * 2);
    float* aldb = att + (rel * 2 + 1) * (NN * 2);
    #pragma unroll
    for (int i = 0; i < 8; i++) {
        float ps = acc[i].x * avs.x + acc[i].y * avs.y + acc[i].z * avs.z + acc[i].w * avs.w;
        float pd = acc[i].x * avd.x + acc[i].y * avd.y + acc[i].z * avd.z + acc[i].w * avd.w;
        #pragma unroll
        for (int o = 8; o; o >>= 1) {
            ps += __shfl_xor_sync(0xffffffffu, ps, o);
            pd += __shfl_xor_sync(0xffffffffu, pd, o);
        }
        if (tx == 0) {
            int row = bm + ty * 8 + i;
            atomicAdd(&alsb[row * 2 + h], ps);
            atomicAdd(&aldb[row * 2 + h], pd);
        }
    }
}

// =======================================================================
// FUSED scan (blocks 0,1) + fill (blocks 2..18), flag-synchronized
// =======================================================================
constexpr int SF_FILL_BLOCKS = 17;   // 16 edge blocks (1024 thr x int4) + 1 self-loop

__global__ void __launch_bounds__(1024)
k_scanfill(const int* __restrict__ ei0, const int* __restrict__ ei1,
           const float* __restrict__ b1_0, const float* __restrict__ b1_1,
           const float* __restrict__ b2_0, const float* __restrict__ b2_1,
           const float* __restrict__ wlin) {
    int b = blockIdx.x;
    int t = threadIdx.x;

    if (b < 2) {
        int r = b;
        __shared__ int sh[NN];
        __shared__ float fred[4];

        int c0 = g_cnt4[0][r][t] + 1;   // self loop in shard 0
        int c1 = g_cnt4[1][r][t];
        int c2 = g_cnt4[2][r][t];
        int c3 = g_cnt4[3][r][t];
        int mine = c0 + c1 + c2 + c3;
        sh[t] = mine;
        __syncthreads();
        #pragma unroll
        for (int d = 1; d < NN; d <<= 1) {
            int v = (t >= d) ? sh[t - d] : 0;
            __syncthreads();
            sh[t] += v;
            __syncthreads();
        }
        g_off[r][t + 1] = sh[t];
        if (t == 0) g_off[r][0] = 0;
        int base = sh[t] - mine;
        g_cur4[0][r][t] = base;
        g_cur4[1][r][t] = base + c0;
        g_cur4[2][r][t] = base + c0 + c1;
        g_cur4[3][r][t] = base + c0 + c1 + c2;

        // side duties
        if (r == 0) {
            if (t < W1O) g_bb[t] = b1_0[t] + b1_1[t];
        } else {
            float p = 0.f;
            if (t < W2O) p = (b2_0[t] + b2_1[t]) * wlin[t];
            if (t < 128) {
                #pragma unroll
                for (int o = 16; o; o >>= 1) p += __shfl_xor_sync(0xffffffffu, p, o);
                if ((t & 31) == 0) fred[t >> 5] = p;
            }
            __syncthreads();
            if (t == 0) g_cbias[0] = fred[0] + fred[1] + fred[2] + fred[3];
        }

        __threadfence();
        __syncthreads();
        if (t == 0) atomicAdd(&g_flag, 1);
        return;
    }

    // ---- fill blocks: wait for both scan blocks ----
    if (t == 0) {
        while (atomicAdd(&g_flag, 0) < 2) {}
    }
    __syncthreads();
    __threadfence();

    int fb = b - 2;
    if (fb < 16) {
        int idx = fb * 1024 + t;     // int4 index; 16*1024 = EE/4
        int4 s0 = ((const int4*)ei0)[idx];
        int4 d0 = ((const int4*)(ei0 + EE))[idx];
        int4 s1 = ((const int4*)ei1)[idx];
        int4 d1 = ((const int4*)(ei1 + EE))[idx];
        int p;
        p = atomicAdd(&g_cur4[0][0][d0.x], 1); g_srcs[0][p] = s0.x;
        p = atomicAdd(&g_cur4[1][0][d0.y], 1); g_srcs[0][p] = s0.y;
        p = atomicAdd(&g_cur4[2][0][d0.z], 1); g_srcs[0][p] = s0.z;
        p = atomicAdd(&g_cur4[3][0][d0.w], 1); g_srcs[0][p] = s0.w;
        p = atomicAdd(&g_cur4[0][1][d1.x], 1); g_srcs[1][p] = s1.x;
        p = atomicAdd(&g_cur4[1][1][d1.y], 1); g_srcs[1][p] = s1.y;
        p = atomicAdd(&g_cur4[2][1][d1.z], 1); g_srcs[1][p] = s1.z;
        p = atomicAdd(&g_cur4[3][1][d1.w], 1); g_srcs[1][p] = s1.w;
    } else {
        int n = t;   // self loops
        int p0 = atomicAdd(&g_cur4[0][0][n], 1); g_srcs[0][p0] = n;
        int p1 = atomicAdd(&g_cur4[0][1][n], 1); g_srcs[1][p1] = n;
    }
}

// =======================================================================
// agg1: block per (dst, rel); fp16 gather; packed float4 edge staging;
// writes NORMALIZED partial (bias+relu+combine deferred into gemm2)
// =======================================================================
__global__ void __launch_bounds__(128)
k_agg1(const __half* __restrict__ xp0, const __half* __restrict__ xp1,
       const float* __restrict__ att,
       const int* __restrict__ off, const int* __restrict__ srcs,
       float* __restrict__ h1a, float* __restrict__ h1b) {
    constexpr int CH = 512;
    __shared__ float4 sh4[CH];   // (src_off_as_int, e0, e1, pad)
    __shared__ float red[8];

    int dst = blockIdx.x, rel = blockIdx.y, t = threadIdx.x;
    const __half* xp    = rel ? xp1 : xp0;
    float*        outp  = rel ? h1b : h1a;
    const float*  alsr  = att + (rel * 2 + 0) * (NN * 2);
    const float*  aldr  = att + (rel * 2 + 1) * (NN * 2);
    const int*    offr  = off + (size_t)rel * (NN + 1);
    const int*    srcsr = srcs + (size_t)rel * E2;

    int head = ((t * 4) >= C1) ? 1 : 0;
    int o0 = offr[dst];
    int range = offr[dst + 1] - o0;
    float ad0 = aldr[dst * 2 + 0], ad1 = aldr[dst * 2 + 1];

    float sum0 = 0.f, sum1 = 0.f;
    float4 a4 = make_float4(0.f, 0.f, 0.f, 0.f);

    for (int base = 0; base < range; base += CH) {
        int nn = min(CH, range - base);
        __syncthreads();
        for (int i = t; i < nn; i += 128) {
            int s = srcsr[o0 + base + i];
            float l0 = alsr[s * 2 + 0] + ad0; l0 = l0 > 0.f ? l0 : 0.2f * l0;
            float l1 = alsr[s * 2 + 1] + ad1; l1 = l1 > 0.f ? l1 : 0.2f * l1;
            float e0 = expf(l0);
            float e1 = expf(l1);
            sh4[i] = make_float4(__int_as_float(s * W1O), e0, e1, 0.f);
            sum0 += e0; sum1 += e1;
        }
        __syncthreads();
        #pragma unroll 4
        for (int j = 0; j < nn; j++) {
            float4 sv = sh4[j];
            float e = head ? sv.z : sv.y;
            const uint2* row = (const uint2*)(xp + __float_as_int(sv.x));
            uint2 v = row[t];
            __half2 h01 = *reinterpret_cast<__half2*>(&v.x);
            __half2 h23 = *reinterpret_cast<__half2*>(&v.y);
            float2 f01 = __half22float2(h01);
            float2 f23 = __half22float2(h23);
            a4.x = fmaf(e, f01.x, a4.x);
            a4.y = fmaf(e, f01.y, a4.y);
            a4.z = fmaf(e, f23.x, a4.z);
            a4.w = fmaf(e, f23.y, a4.w);
        }
    }
    #pragma unroll
    for (int o = 16; o; o >>= 1) {
        sum0 += __shfl_xor_sync(0xffffffffu, sum0, o);
        sum1 += __shfl_xor_sync(0xffffffffu, sum1, o);
    }
    if ((t & 31) == 0) { red[t >> 5] = sum0; red[4 + (t >> 5)] = sum1; }
    __syncthreads();
    sum0 = red[0] + red[1] + red[2] + red[3];
    sum1 = red[4] + red[5] + red[6] + red[7];
    float inv = head ? 1.f / (sum1 + 1e-16f) : 1.f / (sum0 + 1e-16f);
    float4 v;
    v.x = a4.x * inv; v.y = a4.y * inv; v.z = a4.z * inv; v.w = a4.w * inv;
    ((float4*)(outp + (size_t)dst * W1O))[t] = v;
}

// =======================================================================
// gemm2: A = relu(h1a + h1b + bb) on the fly; f32x2 math; attn2 epilogue
// =======================================================================
DEV_INLINE float4 ld_h1(const float* __restrict__ h1a, const float* __restrict__ h1b,
                        size_t row, int k) {
    float4 a = *(const float4*)(h1a + row * W1O + k);
    float4 b = *(const float4*)(h1b + row * W1O + k);
    float4 c = *(const float4*)(g_bb + k);
    float4 v;
    v.x = a.x + b.x + c.x; v.x = v.x > 0.f ? v.x : 0.f;
    v.y = a.y + b.y + c.y; v.y = v.y > 0.f ? v.y : 0.f;
    v.z = a.z + b.z + c.z; v.z = v.z > 0.f ? v.z : 0.f;
    v.w = a.w + b.w + c.w; v.w = v.w > 0.f ? v.w : 0.f;
    return v;
}

__global__ void __launch_bounds__(128)
k_gemm2(const float* __restrict__ h1a, const float* __restrict__ h1b,
        const float* __restrict__ B0, const float* __restrict__ B1,
        float* __restrict__ Co0, float* __restrict__ Co1,
        const float* __restrict__ as0, const float* __restrict__ as1,
        const float* __restrict__ ad0, const float* __restrict__ ad1,
        float* __restrict__ att) {
    constexpr int K = 512, Nc = W2O;
    __shared__ float smem[16 * 128 + 16 * 32];   // As_dup (8KB) + Bs (2KB)
    float* Asd = smem;             // [16][128] duplicated pairs
    float* Bs  = smem + 16 * 128;  // [16][32]

    int bid = blockIdx.x;
    int rel = bid >> 6;
    int r   = bid & 63;
    int bn  = (r & 3) * 32;
    int bm  = (r >> 2) * 64;
    const float* B = rel ? B1 : B0;
    float*       C = rel ? Co1 : Co0;

    int t = threadIdx.x;
    int tx = t & 7, ty = t >> 3;
    int am = t >> 2, ak = (t & 3) * 4;

    unsigned long long acc2[4][2];
    #pragma unroll
    for (int i = 0; i < 4; i++) { acc2[i][0] = 0ULL; acc2[i][1] = 0ULL; }

    float4 a_reg0 = ld_h1(h1a, h1b, (size_t)(bm + am), ak);
    float4 a_reg1 = ld_h1(h1a, h1b, (size_t)(bm + am + 32), ak);
    float4 b_reg  = *(const float4*)(B + (size_t)(t >> 3) * Nc + bn + (t & 7) * 4);

    for (int k0 = 0; k0 < K; k0 += 16) {
        {
            float a0[4] = {a_reg0.x, a_reg0.y, a_reg0.z, a_reg0.w};
            float a1[4] = {a_reg1.x, a_reg1.y, a_reg1.z, a_reg1.w};
            #pragma unroll
            for (int j = 0; j < 4; j++) {
                ((unsigned long long*)(Asd + (ak + j) * 128))[am]      = dup2(a0[j]);
                ((unsigned long long*)(Asd + (ak + j) * 128))[am + 32] = dup2(a1[j]);
            }
        }
        ((float4*)(Bs + (t >> 3) * 32))[t & 7] = b_reg;
        __syncthreads();

        if (k0 + 16 < K) {
            a_reg0 = ld_h1(h1a, h1b, (size_t)(bm + am), k0 + 16 + ak);
            a_reg1 = ld_h1(h1a, h1b, (size_t)(bm + am + 32), k0 + 16 + ak);
            b_reg  = *(const float4*)(B + (size_t)(k0 + 16 + (t >> 3)) * Nc + bn + (t & 7) * 4);
        }

        #pragma unroll
        for (int k = 0; k < 16; k++) {
            const unsigned long long* ad =
                (const unsigned long long*)(Asd + k * 128) + ty * 4;
            unsigned long long b01 = ((const unsigned long long*)(Bs + k * 32))[tx * 2];
            unsigned long long b23 = ((const unsigned long long*)(Bs + k * 32))[tx * 2 + 1];
            #pragma unroll
            for (int i = 0; i < 4; i++) {
                fma2(acc2[i][0], ad[i], b01);
                fma2(acc2[i][1], ad[i], b23);
            }
        }
        __syncthreads();
    }

    float4 acc[4];
    #pragma unroll
    for (int i = 0; i < 4; i++) {
        float2 p = unpack2(acc2[i][0]);
        float2 q = unpack2(acc2[i][1]);
        acc[i] = make_float4(p.x, p.y, q.x, q.y);
    }

    #pragma unroll
    for (int i = 0; i < 4; i++)
        *(float4*)(C + (size_t)(bm + ty * 4 + i) * Nc + bn + tx * 4) = acc[i];

    // fused attn2 logit partials
    const float* asrc = rel ? as1 : as0;
    const float* adst = rel ? ad1 : ad0;
    int h   = bn >> 6;
    int cin = (bn & 63) + tx * 4;
    float4 avs = *(const float4*)(asrc + h * C2 + cin);
    float4 avd = *(const float4*)(adst + h * C2 + cin);
    float* alsb = att + (rel * 2 + 0) * (NN * 2);
    float* aldb = att + (rel * 2 + 1) * (NN * 2);
    #pragma unroll
    for (int i = 0; i < 4; i++) {
        float ps = acc[i].x * avs.x + acc[i].y * avs.y + acc[i].z * avs.z + acc[i].w * avs.w;
        float pd = acc[i].x * avd.x + acc[i].y * avd.y + acc[i].z * avd.z + acc[i].w * avd.w;
        #pragma unroll
        for (int o = 4; o; o >>= 1) {
            ps += __shfl_xor_sync(0xffffffffu, ps, o);
            pd += __shfl_xor_sync(0xffffffffu, pd, o);
        }
        if (tx == 0) {
            int row = bm + ty * 4 + i;
            atomicAdd(&alsb[row * 2 + h], ps);
            atomicAdd(&aldb[row * 2 + h], pd);
        }
    }
}

// =======================================================================
// agg2: block per (dst, rel); plain-store per-relation partial s
// =======================================================================
__global__ void __launch_bounds__(128)
k_agg2(const float* __restrict__ xp0, const float* __restrict__ xp1,
       const float* __restrict__ att,
       const int* __restrict__ off, const int* __restrict__ srcs,
       const float* __restrict__ wlin) {
    constexpr int CH = 512;
    __shared__ float4 sh4[CH];
    __shared__ float red[8];

    int dst = blockIdx.x, rel = blockIdx.y, t = threadIdx.x;
    const float* xp    = rel ? xp1 : xp0;
    const float* alsr  = att + (rel * 2 + 0) * (NN * 2);
    const float* aldr  = att + (rel * 2 + 1) * (NN * 2);
    const int*   offr  = off + (size_t)rel * (NN + 1);
    const int*   srcsr = srcs + (size_t)rel * E2;

    int head = (t >= C2) ? 1 : 0;
    int o0 = offr[dst];
    int range = offr[dst + 1] - o0;
    float ad0 = aldr[dst * 2 + 0], ad1 = aldr[dst * 2 + 1];

    float sum0 = 0.f, sum1 = 0.f;
    float a1 = 0.f;

    for (int base = 0; base < range; base += CH) {
        int nn = min(CH, range - base);
        __syncthreads();
        for (int i = t; i < nn; i += 128) {
            int s = srcsr[o0 + base + i];
            float l0 = alsr[s * 2 + 0] + ad0; l0 = l0 > 0.f ? l0 : 0.2f * l0;
            float l1 = alsr[s * 2 + 1] + ad1; l1 = l1 > 0.f ? l1 : 0.2f * l1;
            float e0 = expf(l0);
            float e1 = expf(l1);
            sh4[i] = make_float4(__int_as_float(s * W2O), e0, e1, 0.f);
            sum0 += e0; sum1 += e1;
        }
        __syncthreads();
        #pragma unroll 4
        for (int j = 0; j < nn; j++) {
            float4 sv = sh4[j];
            float e = head ? sv.z : sv.y;
            a1 = fmaf(e, xp[__float_as_int(sv.x) + t], a1);
        }
    }
    #pragma unroll
    for (int o = 16; o; o >>= 1) {
        sum0 += __shfl_xor_sync(0xffffffffu, sum0, o);
        sum1 += __shfl_xor_sync(0xffffffffu, sum1, o);
    }
    if ((t & 31) == 0) { red[t >> 5] = sum0; red[4 + (t >> 5)] = sum1; }
    __syncthreads();
    sum0 = red[0] + red[1] + red[2] + red[3];
    sum1 = red[4] + red[5] + red[6] + red[7];
    float inv = head ? 1.f / (sum1 + 1e-16f) : 1.f / (sum0 + 1e-16f);
    float p = a1 * inv * wlin[t];
    #pragma unroll
    for (int o = 16; o; o >>= 1) p += __shfl_xor_sync(0xffffffffu, p, o);
    __syncthreads();
    if ((t & 31) == 0) red[t >> 5] = p;
    __syncthreads();
    if (t == 0) g_s2[rel][dst] = red[0] + red[1] + red[2] + red[3];
}

// ---------------- pairwise output: out[i*N+j] = s[i]+s[j]+2*cbias+b -------
__global__ void k_pair(float* __restrict__ out, const float* __restrict__ blin) {
    int idx = blockIdx.x * blockDim.x + threadIdx.x;
    float b = blin[0] + 2.f * g_cbias[0];
    int i = idx >> 8;
    int j4 = (idx & 255) << 2;
    float si = g_s2[0][i] + g_s2[1][i] + b;
    float4 v;
    v.x = si + g_s2[0][j4 + 0] + g_s2[1][j4 + 0];
    v.y = si + g_s2[0][j4 + 1] + g_s2[1][j4 + 1];
    v.z = si + g_s2[0][j4 + 2] + g_s2[1][j4 + 2];
    v.w = si + g_s2[0][j4 + 3] + g_s2[1][j4 + 3];
    ((float4*)out)[idx] = v;
}

// ---------------- launch ----------------
extern "C" void kernel_launch(void* const* d_in, const int* in_sizes, int n_in,
                              void* d_out, int out_size) {
    const float* x    = (const float*)d_in[0];
    const int*   ei0  = (const int*)d_in[1];
    const int*   ei1  = (const int*)d_in[2];
    const float* W1[2]  = {(const float*)d_in[3],  (const float*)d_in[7]};
    const float* as1[2] = {(const float*)d_in[4],  (const float*)d_in[8]};
    const float* ad1[2] = {(const float*)d_in[5],  (const float*)d_in[9]};
    const float* b1[2]  = {(const float*)d_in[6],  (const float*)d_in[10]};
    const float* W2[2]  = {(const float*)d_in[11], (const float*)d_in[15]};
    const float* as2[2] = {(const float*)d_in[12], (const float*)d_in[16]};
    const float* ad2[2] = {(const float*)d_in[13], (const float*)d_in[17]};
    const float* b2[2]  = {(const float*)d_in[14], (const float*)d_in[18]};
    const float* wlin = (const float*)d_in[19];
    const float* blin = (const float*)d_in[20];
    float* out = (float*)d_out;

    float *xp, *h1a, *h1b, *attp;
    __half* xph;
    int *cnt4p, *offp, *srcsp;
    cudaGetSymbolAddress((void**)&xph,   g_xph);
    cudaGetSymbolAddress((void**)&xp,    g_xp);
    cudaGetSymbolAddress((void**)&h1a,   g_h1a);
    cudaGetSymbolAddress((void**)&h1b,   g_h1b);
    cudaGetSymbolAddress((void**)&attp,  g_att);
    cudaGetSymbolAddress((void**)&cnt4p, g_cnt4);
    cudaGetSymbolAddress((void**)&offp,  g_off);
    cudaGetSymbolAddress((void**)&srcsp, g_srcs);

    __half* xph0 = xph;
    __half* xph1 = xph + (size_t)NN * W1O;
    float*  xp0  = xp;
    float*  xp1  = xp + (size_t)NN * W2O;
    float*  att1 = attp;
    float*  att2 = attp + (2 * 2 * NN * 2);

    cudaMemsetAsync(cnt4p, 0, 4 * 2 * NN * sizeof(int));
    cudaMemsetAsync(attp, 0, 2 * (2 * 2 * NN * 2) * sizeof(float));

    // gemm1 (fp16 out, f32x2 math, +attn1 epilogue) + sharded count
    k_gemm1_count<<<G1_GEMM_BLOCKS + G1_COUNT_BLOCKS, 256>>>(
        x, W1[0], W1[1], xph0, xph1, ei0, ei1,
        as1[0], as1[1], ad1[0], ad1[1], att1);

    // fused scan + fill
    k_scanfill<<<2 + SF_FILL_BLOCKS, 1024>>>(
        ei0, ei1, b1[0], b1[1], b2[0], b2[1], wlin);

    // layer-1 aggregation
    k_agg1<<<dim3(NN, 2), 128>>>(xph0, xph1, att1, offp, srcsp, h1a, h1b);

    // gemm2 (f32x2 math, relu(h1a+h1b+bb) A-load, +attn2 epilogue)
    k_gemm2<<<128, 128>>>(h1a, h1b, W2[0], W2[1], xp0, xp1,
                          as2[0], as2[1], ad2[0], ad2[1], att2);

    // layer-2 aggregation -> per-relation s partials
    k_agg2<<<dim3(NN, 2), 128>>>(xp0, xp1, att2, offp, srcsp, wlin);

    k_pair<<<NN * NN / 4 / 256, 256>>>(out, blin);
}

// round 10
// speedup vs baseline: 1.1736x; 1.1736x over previous
#include <cuda_runtime.h>
#include <cuda_fp16.h>

#define DEV_INLINE __device__ __forceinline__

constexpr int NN   = 1024;
constexpr int EE   = 65536;
constexpr int E2   = EE + NN;      // edges + self loops
constexpr int W1O  = 512;          // H*256
constexpr int C1   = 256;
constexpr int W2O  = 128;          // H*64
constexpr int C2   = 64;

// ---------------- scratch (device globals) -------------
__device__ __half g_xph[2][NN * W1O];   // layer-1 projected features (fp16)
__device__ float  g_xp[2][NN * W2O];    // layer-2 projected features (fp32)
__device__ float  g_h1a[NN * W1O];      // layer-1 partial (rel 0, normalized)
__device__ float  g_h1b[NN * W1O];      // layer-1 partial (rel 1, normalized)
__device__ float  g_bb[W1O];            // b1_0+b1_1
__device__ float  g_cbias[1];           // sum((b2_0+b2_1)*wlin)
__device__ float  g_att[2][2 * 2 * NN * 2];  // [layer][rel][als/ald][node*2+head]
__device__ int    g_cnt4[4][2][NN];     // sharded edge counts
__device__ int    g_cur4[4][2][NN];     // sharded fill cursors
__device__ int    g_off[2][NN + 1];
__device__ int    g_srcs[2][E2];
__device__ float  g_s2[2][NN];          // per-relation score partials
__device__ int    g_flag;               // scan-done flag

// =======================================================================
// FUSED: gemm1 (both relations, fp16 out) + attn1 logits + sharded count
// (round-8 plain-FFMA GEMM body)
// =======================================================================
constexpr int G1_GEMM_BLOCKS  = (W1O / 64) * (NN / 128) * 2;   // 128
constexpr int G1_COUNT_BLOCKS = EE / 4 / 256;                  // 64

__global__ void __launch_bounds__(256)
k_gemm1_count(const float* __restrict__ A,
              const float* __restrict__ B0, const float* __restrict__ B1,
              __half* __restrict__ Ch0, __half* __restrict__ Ch1,
              const int* __restrict__ ei0, const int* __restrict__ ei1,
              const float* __restrict__ as0, const float* __restrict__ as1,
              const float* __restrict__ ad0, const float* __restrict__ ad1,
              float* __restrict__ att) {
    int bid = blockIdx.x;
    int t = threadIdx.x;

    if (bid >= G1_GEMM_BLOCKS) {
        if (bid == G1_GEMM_BLOCKS && t == 0) g_flag = 0;   // reset for scanfill
        int cid = bid - G1_GEMM_BLOCKS;
        int idx = cid * 256 + t;
        int4 d0 = ((const int4*)(ei0 + EE))[idx];
        int4 d1 = ((const int4*)(ei1 + EE))[idx];
        atomicAdd(&g_cnt4[0][0][d0.x], 1); atomicAdd(&g_cnt4[1][0][d0.y], 1);
        atomicAdd(&g_cnt4[2][0][d0.z], 1); atomicAdd(&g_cnt4[3][0][d0.w], 1);
        atomicAdd(&g_cnt4[0][1][d1.x], 1); atomicAdd(&g_cnt4[1][1][d1.y], 1);
        atomicAdd(&g_cnt4[2][1][d1.z], 1); atomicAdd(&g_cnt4[3][1][d1.w], 1);
        return;
    }

    constexpr int K = 256, Nc = W1O;
    __shared__ float4 sh[768];
    float*  As  = (float*)sh;
    float4* As4 = sh;                            // row stride 32
    float4* Bs4 = sh + 512;                      // [16][16]

    int rel = bid >> 6;
    int r   = bid & 63;
    int bn  = (r & 7) * 64;
    int bm  = (r >> 3) * 128;
    const float* B = rel ? B1 : B0;
    __half*      Ch = rel ? Ch1 : Ch0;

    int tx = t & 15, ty = t >> 4;
    int am = t >> 2, ak = (t & 3) * 4;

    float4 acc[8];
    #pragma unroll
    for (int i = 0; i < 8; i++) acc[i] = make_float4(0.f, 0.f, 0.f, 0.f);

    float4 a_reg0 = *(const float4*)(A + (size_t)(bm + am) * K + ak);
    float4 a_reg1 = *(const float4*)(A + (size_t)(bm + am + 64) * K + ak);
    float4 b_reg  = *(const float4*)(B + (size_t)(t >> 4) * Nc + bn + (t & 15) * 4);

    for (int k0 = 0; k0 < K; k0 += 16) {
        As[(ak + 0) * 128 + am] = a_reg0.x;
        As[(ak + 1) * 128 + am] = a_reg0.y;
        As[(ak + 2) * 128 + am] = a_reg0.z;
        As[(ak + 3) * 128 + am] = a_reg0.w;
        As[(ak + 0) * 128 + am + 64] = a_reg1.x;
        As[(ak + 1) * 128 + am + 64] = a_reg1.y;
        As[(ak + 2) * 128 + am + 64] = a_reg1.z;
        As[(ak + 3) * 128 + am + 64] = a_reg1.w;
        Bs4[(t >> 4) * 16 + (t & 15)] = b_reg;
        __syncthreads();

        if (k0 + 16 < K) {
            a_reg0 = *(const float4*)(A + (size_t)(bm + am) * K + k0 + 16 + ak);
            a_reg1 = *(const float4*)(A + (size_t)(bm + am + 64) * K + k0 + 16 + ak);
            b_reg  = *(const float4*)(B + (size_t)(k0 + 16 + (t >> 4)) * Nc + bn + (t & 15) * 4);
        }

        #pragma unroll
        for (int k = 0; k < 16; k++) {
            float4 a0 = As4[k * 32 + ty * 2];
            float4 a1 = As4[k * 32 + ty * 2 + 1];
            float4 b  = Bs4[k * 16 + tx];
            float ar[8] = {a0.x, a0.y, a0.z, a0.w, a1.x, a1.y, a1.z, a1.w};
            #pragma unroll
            for (int i = 0; i < 8; i++) {
                acc[i].x = fmaf(ar[i], b.x, acc[i].x);
                acc[i].y = fmaf(ar[i], b.y, acc[i].y);
                acc[i].z = fmaf(ar[i], b.z, acc[i].z);
                acc[i].w = fmaf(ar[i], b.w, acc[i].w);
            }
        }
        __syncthreads();
    }
    #pragma unroll
    for (int i = 0; i < 8; i++) {
        __half2 h01 = __floats2half2_rn(acc[i].x, acc[i].y);
        __half2 h23 = __floats2half2_rn(acc[i].z, acc[i].w);
        uint2 v;
        v.x = *reinterpret_cast<unsigned*>(&h01);
        v.y = *reinterpret_cast<unsigned*>(&h23);
        ((uint2*)(Ch + (size_t)(bm + ty * 8 + i) * Nc))[(bn >> 2) + tx] = v;
    }

    // fused attn1 logit partials
    const float* asrc = rel ? as1 : as0;
    const float* adst = rel ? ad1 : ad0;
    int h   = bn >> 8;
    int cin = (bn & 255) + tx * 4;
    float4 avs = *(const float4*)(asrc + h * C1 + cin);
    float4 avd = *(const float4*)(adst + h * C1 + cin);
    float* alsb = att + (rel * 2 + 0) * (NN * 2);
    float* aldb = att + (rel * 2 + 1) * (NN * 2);
    #pragma unroll
    for (int i = 0; i < 8; i++) {
        float ps = acc[i].x * avs.x + acc[i].y * avs.y + acc[i].z * avs.z + acc[i].w * avs.w;
        float pd = acc[i].x * avd.x + acc[i].y * avd.y + acc[i].z * avd.z + acc[i].w * avd.w;
        #pragma unroll
        for (int o = 8; o; o >>= 1) {
            ps += __shfl_xor_sync(0xffffffffu, ps, o);
            pd += __shfl_xor_sync(0xffffffffu, pd, o);
        }
        if (tx == 0) {
            int row = bm + ty * 8 + i;
            atomicAdd(&alsb[row * 2 + h], ps);
            atomicAdd(&aldb[row * 2 + h], pd);
        }
    }
}

// =======================================================================
// FUSED scan (blocks 0,1) + fill (blocks 2..18), flag-synchronized
// =======================================================================
constexpr int SF_FILL_BLOCKS = 17;   // 16 edge blocks (1024 thr x int4) + 1 self-loop

__global__ void __launch_bounds__(1024)
k_scanfill(const int* __restrict__ ei0, const int* __restrict__ ei1,
           const float* __restrict__ b1_0, const float* __restrict__ b1_1,
           const float* __restrict__ b2_0, const float* __restrict__ b2_1,
           const float* __restrict__ wlin) {
    int b = blockIdx.x;
    int t = threadIdx.x;

    if (b < 2) {
        int r = b;
        __shared__ int sh[NN];
        __shared__ float fred[4];

        int c0 = g_cnt4[0][r][t] + 1;   // self loop in shard 0
        int c1 = g_cnt4[1][r][t];
        int c2 = g_cnt4[2][r][t];
        int c3 = g_cnt4[3][r][t];
        int mine = c0 + c1 + c2 + c3;
        sh[t] = mine;
        __syncthreads();
        #pragma unroll
        for (int d = 1; d < NN; d <<= 1) {
            int v = (t >= d) ? sh[t - d] : 0;
            __syncthreads();
            sh[t] += v;
            __syncthreads();
        }
        g_off[r][t + 1] = sh[t];
        if (t == 0) g_off[r][0] = 0;
        int base = sh[t] - mine;
        g_cur4[0][r][t] = base;
        g_cur4[1][r][t] = base + c0;
        g_cur4[2][r][t] = base + c0 + c1;
        g_cur4[3][r][t] = base + c0 + c1 + c2;

        // side duties
        if (r == 0) {
            if (t < W1O) g_bb[t] = b1_0[t] + b1_1[t];
        } else {
            float p = 0.f;
            if (t < W2O) p = (b2_0[t] + b2_1[t]) * wlin[t];
            if (t < 128) {
                #pragma unroll
                for (int o = 16; o; o >>= 1) p += __shfl_xor_sync(0xffffffffu, p, o);
                if ((t & 31) == 0) fred[t >> 5] = p;
            }
            __syncthreads();
            if (t == 0) g_cbias[0] = fred[0] + fred[1] + fred[2] + fred[3];
        }

        __threadfence();
        __syncthreads();
        if (t == 0) atomicAdd(&g_flag, 1);
        return;
    }

    // ---- fill blocks: wait for both scan blocks ----
    if (t == 0) {
        while (atomicAdd(&g_flag, 0) < 2) {}
    }
    __syncthreads();
    __threadfence();

    int fb = b - 2;
    if (fb < 16) {
        int idx = fb * 1024 + t;     // int4 index; 16*1024 = EE/4
        int4 s0 = ((const int4*)ei0)[idx];
        int4 d0 = ((const int4*)(ei0 + EE))[idx];
        int4 s1 = ((const int4*)ei1)[idx];
        int4 d1 = ((const int4*)(ei1 + EE))[idx];
        int p;
        p = atomicAdd(&g_cur4[0][0][d0.x], 1); g_srcs[0][p] = s0.x;
        p = atomicAdd(&g_cur4[1][0][d0.y], 1); g_srcs[0][p] = s0.y;
        p = atomicAdd(&g_cur4[2][0][d0.z], 1); g_srcs[0][p] = s0.z;
        p = atomicAdd(&g_cur4[3][0][d0.w], 1); g_srcs[0][p] = s0.w;
        p = atomicAdd(&g_cur4[0][1][d1.x], 1); g_srcs[1][p] = s1.x;
        p = atomicAdd(&g_cur4[1][1][d1.y], 1); g_srcs[1][p] = s1.y;
        p = atomicAdd(&g_cur4[2][1][d1.z], 1); g_srcs[1][p] = s1.z;
        p = atomicAdd(&g_cur4[3][1][d1.w], 1); g_srcs[1][p] = s1.w;
    } else {
        int n = t;   // self loops
        int p0 = atomicAdd(&g_cur4[0][0][n], 1); g_srcs[0][p0] = n;
        int p1 = atomicAdd(&g_cur4[0][1][n], 1); g_srcs[1][p1] = n;
    }
}

// =======================================================================
// agg1: block per (dst, rel); fp16 gather; writes NORMALIZED partial
// =======================================================================
__global__ void __launch_bounds__(128)
k_agg1(const __half* __restrict__ xp0, const __half* __restrict__ xp1,
       const float* __restrict__ att,
       const int* __restrict__ off, const int* __restrict__ srcs,
       float* __restrict__ h1a, float* __restrict__ h1b) {
    constexpr int CH = 512;
    __shared__ int   sh_src[CH];
    __shared__ float sh_e[2][CH];
    __shared__ float red[8];

    int dst = blockIdx.x, rel = blockIdx.y, t = threadIdx.x;
    const __half* xp    = rel ? xp1 : xp0;
    float*        outp  = rel ? h1b : h1a;
    const float*  alsr  = att + (rel * 2 + 0) * (NN * 2);
    const float*  aldr  = att + (rel * 2 + 1) * (NN * 2);
    const int*    offr  = off + (size_t)rel * (NN + 1);
    const int*    srcsr = srcs + (size_t)rel * E2;

    int head = ((t * 4) >= C1) ? 1 : 0;
    int o0 = offr[dst];
    int range = offr[dst + 1] - o0;
    float ad0 = aldr[dst * 2 + 0], ad1 = aldr[dst * 2 + 1];

    float sum0 = 0.f, sum1 = 0.f;
    float4 a4 = make_float4(0.f, 0.f, 0.f, 0.f);

    for (int base = 0; base < range; base += CH) {
        int nn = min(CH, range - base);
        __syncthreads();
        for (int i = t; i < nn; i += 128) {
            int s = srcsr[o0 + base + i];
            sh_src[i] = s;
            float l0 = alsr[s * 2 + 0] + ad0; l0 = l0 > 0.f ? l0 : 0.2f * l0;
            float l1 = alsr[s * 2 + 1] + ad1; l1 = l1 > 0.f ? l1 : 0.2f * l1;
            float e0 = expf(l0);
            float e1 = expf(l1);
            sh_e[0][i] = e0; sh_e[1][i] = e1;
            sum0 += e0; sum1 += e1;
        }
        __syncthreads();
        const float* eh = sh_e[head];
        #pragma unroll 4
        for (int j = 0; j < nn; j++) {
            int s = sh_src[j];
            float e = eh[j];
            uint2 v = ((const uint2*)(xp + (size_t)s * W1O))[t];
            __half2 h01 = *reinterpret_cast<__half2*>(&v.x);
            __half2 h23 = *reinterpret_cast<__half2*>(&v.y);
            float2 f01 = __half22float2(h01);
            float2 f23 = __half22float2(h23);
            a4.x = fmaf(e, f01.x, a4.x);
            a4.y = fmaf(e, f01.y, a4.y);
            a4.z = fmaf(e, f23.x, a4.z);
            a4.w = fmaf(e, f23.y, a4.w);
        }
    }
    #pragma unroll
    for (int o = 16; o; o >>= 1) {
        sum0 += __shfl_xor_sync(0xffffffffu, sum0, o);
        sum1 += __shfl_xor_sync(0xffffffffu, sum1, o);
    }
    if ((t & 31) == 0) { red[t >> 5] = sum0; red[4 + (t >> 5)] = sum1; }
    __syncthreads();
    sum0 = red[0] + red[1] + red[2] + red[3];
    sum1 = red[4] + red[5] + red[6] + red[7];
    float inv = head ? 1.f / (sum1 + 1e-16f) : 1.f / (sum0 + 1e-16f);
    float4 v;
    v.x = a4.x * inv; v.y = a4.y * inv; v.z = a4.z * inv; v.w = a4.w * inv;
    ((float4*)(outp + (size_t)dst * W1O))[t] = v;
}

// =======================================================================
// gemm2: A = relu(h1a + h1b + bb) on the fly (round-8 plain-FFMA body);
// fused attn2 logit epilogue
// =======================================================================
DEV_INLINE float4 ld_h1(const float* __restrict__ h1a, const float* __restrict__ h1b,
                        size_t row, int k) {
    float4 a = *(const float4*)(h1a + row * W1O + k);
    float4 b = *(const float4*)(h1b + row * W1O + k);
    float4 c = *(const float4*)(g_bb + k);
    float4 v;
    v.x = a.x + b.x + c.x; v.x = v.x > 0.f ? v.x : 0.f;
    v.y = a.y + b.y + c.y; v.y = v.y > 0.f ? v.y : 0.f;
    v.z = a.z + b.z + c.z; v.z = v.z > 0.f ? v.z : 0.f;
    v.w = a.w + b.w + c.w; v.w = v.w > 0.f ? v.w : 0.f;
    return v;
}

__global__ void __launch_bounds__(128)
k_gemm2(const float* __restrict__ h1a, const float* __restrict__ h1b,
        const float* __restrict__ B0, const float* __restrict__ B1,
        float* __restrict__ Co0, float* __restrict__ Co1,
        const float* __restrict__ as0, const float* __restrict__ as1,
        const float* __restrict__ ad0, const float* __restrict__ ad1,
        float* __restrict__ att) {
    constexpr int K = 512, Nc = W2O;
    __shared__ float4 sh[384];
    float*  As  = (float*)sh;
    float4* As4 = sh;                            // row stride 16
    float4* Bs4 = sh + 256;                      // [16][8]

    int bid = blockIdx.x;
    int rel = bid >> 6;
    int r   = bid & 63;
    int bn  = (r & 3) * 32;
    int bm  = (r >> 2) * 64;
    const float* B = rel ? B1 : B0;
    float*       C = rel ? Co1 : Co0;

    int t = threadIdx.x;
    int tx = t & 7, ty = t >> 3;
    int am = t >> 2, ak = (t & 3) * 4;

    float4 acc[4];
    #pragma unroll
    for (int i = 0; i < 4; i++) acc[i] = make_float4(0.f, 0.f, 0.f, 0.f);

    float4 a_reg0 = ld_h1(h1a, h1b, (size_t)(bm + am), ak);
    float4 a_reg1 = ld_h1(h1a, h1b, (size_t)(bm + am + 32), ak);
    float4 b_reg  = *(const float4*)(B + (size_t)(t >> 3) * Nc + bn + (t & 7) * 4);

    for (int k0 = 0; k0 < K; k0 += 16) {
        As[(ak + 0) * 64 + am] = a_reg0.x;
        As[(ak + 1) * 64 + am] = a_reg0.y;
        As[(ak + 2) * 64 + am] = a_reg0.z;
        As[(ak + 3) * 64 + am] = a_reg0.w;
        As[(ak + 0) * 64 + am + 32] = a_reg1.x;
        As[(ak + 1) * 64 + am + 32] = a_reg1.y;
        As[(ak + 2) * 64 + am + 32] = a_reg1.z;
        As[(ak + 3) * 64 + am + 32] = a_reg1.w;
        Bs4[(t >> 3) * 8 + (t & 7)] = b_reg;
        __syncthreads();

        if (k0 + 16 < K) {
            a_reg0 = ld_h1(h1a, h1b, (size_t)(bm + am), k0 + 16 + ak);
            a_reg1 = ld_h1(h1a, h1b, (size_t)(bm + am + 32), k0 + 16 + ak);
            b_reg  = *(const float4*)(B + (size_t)(k0 + 16 + (t >> 3)) * Nc + bn + (t & 7) * 4);
        }

        #pragma unroll
        for (int k = 0; k < 16; k++) {
            float4 a = As4[k * 16 + ty];
            float4 b = Bs4[k * 8 + tx];
            float ar[4] = {a.x, a.y, a.z, a.w};
            #pragma unroll
            for (int i = 0; i < 4; i++) {
                acc[i].x = fmaf(ar[i], b.x, acc[i].x);
                acc[i].y = fmaf(ar[i], b.y, acc[i].y);
                acc[i].z = fmaf(ar[i], b.z, acc[i].z);
                acc[i].w = fmaf(ar[i], b.w, acc[i].w);
            }
        }
        __syncthreads();
    }
    #pragma unroll
    for (int i = 0; i < 4; i++)
        *(float4*)(C + (size_t)(bm + ty * 4 + i) * Nc + bn + tx * 4) = acc[i];

    // fused attn2 logit partials
    const float* asrc = rel ? as1 : as0;
    const float* adst = rel ? ad1 : ad0;
    int h   = bn >> 6;
    int cin = (bn & 63) + tx * 4;
    float4 avs = *(const float4*)(asrc + h * C2 + cin);
    float4 avd = *(const float4*)(adst + h * C2 + cin);
    float* alsb = att + (rel * 2 + 0) * (NN * 2);
    float* aldb = att + (rel * 2 + 1) * (NN * 2);
    #pragma unroll
    for (int i = 0; i < 4; i++) {
        float ps = acc[i].x * avs.x + acc[i].y * avs.y + acc[i].z * avs.z + acc[i].w * avs.w;
        float pd = acc[i].x * avd.x + acc[i].y * avd.y + acc[i].z * avd.z + acc[i].w * avd.w;
        #pragma unroll
        for (int o = 4; o; o >>= 1) {
            ps += __shfl_xor_sync(0xffffffffu, ps, o);
            pd += __shfl_xor_sync(0xffffffffu, pd, o);
        }
        if (tx == 0) {
            int row = bm + ty * 4 + i;
            atomicAdd(&alsb[row * 2 + h], ps);
            atomicAdd(&aldb[row * 2 + h], pd);
        }
    }
}

// =======================================================================
// agg2: block per (dst, rel); plain-store per-relation partial s
// =======================================================================
__global__ void __launch_bounds__(128)
k_agg2(const float* __restrict__ xp0, const float* __restrict__ xp1,
       const float* __restrict__ att,
       const int* __restrict__ off, const int* __restrict__ srcs,
       const float* __restrict__ wlin) {
    constexpr int CH = 512;
    __shared__ int   sh_src[CH];
    __shared__ float sh_e[2][CH];
    __shared__ float red[8];

    int dst = blockIdx.x, rel = blockIdx.y, t = threadIdx.x;
    const float* xp    = rel ? xp1 : xp0;
    const float* alsr  = att + (rel * 2 + 0) * (NN * 2);
    const float* aldr  = att + (rel * 2 + 1) * (NN * 2);
    const int*   offr  = off + (size_t)rel * (NN + 1);
    const int*   srcsr = srcs + (size_t)rel * E2;

    int head = (t >= C2) ? 1 : 0;
    int o0 = offr[dst];
    int range = offr[dst + 1] - o0;
    float ad0 = aldr[dst * 2 + 0], ad1 = aldr[dst * 2 + 1];

    float sum0 = 0.f, sum1 = 0.f;
    float a1 = 0.f;

    for (int base = 0; base < range; base += CH) {
        int nn = min(CH, range - base);
        __syncthreads();
        for (int i = t; i < nn; i += 128) {
            int s = srcsr[o0 + base + i];
            sh_src[i] = s;
            float l0 = alsr[s * 2 + 0] + ad0; l0 = l0 > 0.f ? l0 : 0.2f * l0;
            float l1 = alsr[s * 2 + 1] + ad1; l1 = l1 > 0.f ? l1 : 0.2f * l1;
            float e0 = expf(l0);
            float e1 = expf(l1);
            sh_e[0][i] = e0; sh_e[1][i] = e1;
            sum0 += e0; sum1 += e1;
        }
        __syncthreads();
        const float* eh = sh_e[head];
        #pragma unroll 4
        for (int j = 0; j < nn; j++) {
            int s = sh_src[j];
            a1 = fmaf(eh[j], xp[(size_t)s * W2O + t], a1);
        }
    }
    #pragma unroll
    for (int o = 16; o; o >>= 1) {
        sum0 += __shfl_xor_sync(0xffffffffu, sum0, o);
        sum1 += __shfl_xor_sync(0xffffffffu, sum1, o);
    }
    if ((t & 31) == 0) { red[t >> 5] = sum0; red[4 + (t >> 5)] = sum1; }
    __syncthreads();
    sum0 = red[0] + red[1] + red[2] + red[3];
    sum1 = red[4] + red[5] + red[6] + red[7];
    float inv = head ? 1.f / (sum1 + 1e-16f) : 1.f / (sum0 + 1e-16f);
    float p = a1 * inv * wlin[t];
    #pragma unroll
    for (int o = 16; o; o >>= 1) p += __shfl_xor_sync(0xffffffffu, p, o);
    __syncthreads();
    if ((t & 31) == 0) red[t >> 5] = p;
    __syncthreads();
    if (t == 0) g_s2[rel][dst] = red[0] + red[1] + red[2] + red[3];
}

// ---------------- pairwise output: out[i*N+j] = s[i]+s[j]+2*cbias+b -------
__global__ void k_pair(float* __restrict__ out, const float* __restrict__ blin) {
    int idx = blockIdx.x * blockDim.x + threadIdx.x;
    float b = blin[0] + 2.f * g_cbias[0];
    int i = idx >> 8;
    int j4 = (idx & 255) << 2;
    float si = g_s2[0][i] + g_s2[1][i] + b;
    float4 v;
    v.x = si + g_s2[0][j4 + 0] + g_s2[1][j4 + 0];
    v.y = si + g_s2[0][j4 + 1] + g_s2[1][j4 + 1];
    v.z = si + g_s2[0][j4 + 2] + g_s2[1][j4 + 2];
    v.w = si + g_s2[0][j4 + 3] + g_s2[1][j4 + 3];
    ((float4*)out)[idx] = v;
}

// ---------------- launch ----------------
extern "C" void kernel_launch(void* const* d_in, const int* in_sizes, int n_in,
                              void* d_out, int out_size) {
    const float* x    = (const float*)d_in[0];
    const int*   ei0  = (const int*)d_in[1];
    const int*   ei1  = (const int*)d_in[2];
    const float* W1[2]  = {(const float*)d_in[3],  (const float*)d_in[7]};
    const float* as1[2] = {(const float*)d_in[4],  (const float*)d_in[8]};
    const float* ad1[2] = {(const float*)d_in[5],  (const float*)d_in[9]};
    const float* b1[2]  = {(const float*)d_in[6],  (const float*)d_in[10]};
    const float* W2[2]  = {(const float*)d_in[11], (const float*)d_in[15]};
    const float* as2[2] = {(const float*)d_in[12], (const float*)d_in[16]};
    const float* ad2[2] = {(const float*)d_in[13], (const float*)d_in[17]};
    const float* b2[2]  = {(const float*)d_in[14], (const float*)d_in[18]};
    const float* wlin = (const float*)d_in[19];
    const float* blin = (const float*)d_in[20];
    float* out = (float*)d_out;

    float *xp, *h1a, *h1b, *attp;
    __half* xph;
    int *cnt4p, *offp, *srcsp;
    cudaGetSymbolAddress((void**)&xph,   g_xph);
    cudaGetSymbolAddress((void**)&xp,    g_xp);
    cudaGetSymbolAddress((void**)&h1a,   g_h1a);
    cudaGetSymbolAddress((void**)&h1b,   g_h1b);
    cudaGetSymbolAddress((void**)&attp,  g_att);
    cudaGetSymbolAddress((void**)&cnt4p, g_cnt4);
    cudaGetSymbolAddress((void**)&offp,  g_off);
    cudaGetSymbolAddress((void**)&srcsp, g_srcs);

    __half* xph0 = xph;
    __half* xph1 = xph + (size_t)NN * W1O;
    float*  xp0  = xp;
    float*  xp1  = xp + (size_t)NN * W2O;
    float*  att1 = attp;
    float*  att2 = attp + (2 * 2 * NN * 2);

    cudaMemsetAsync(cnt4p, 0, 4 * 2 * NN * sizeof(int));
    cudaMemsetAsync(attp, 0, 2 * (2 * 2 * NN * 2) * sizeof(float));

    // gemm1 (fp16 out, +attn1 epilogue) + sharded count
    k_gemm1_count<<<G1_GEMM_BLOCKS + G1_COUNT_BLOCKS, 256>>>(
        x, W1[0], W1[1], xph0, xph1, ei0, ei1,
        as1[0], as1[1], ad1[0], ad1[1], att1);

    // fused scan + fill
    k_scanfill<<<2 + SF_FILL_BLOCKS, 1024>>>(
        ei0, ei1, b1[0], b1[1], b2[0], b2[1], wlin);

    // layer-1 aggregation
    k_agg1<<<dim3(NN, 2), 128>>>(xph0, xph1, att1, offp, srcsp, h1a, h1b);

    // gemm2 (relu(h1a+h1b+bb) A-load, +attn2 epilogue)
    k_gemm2<<<128, 128>>>(h1a, h1b, W2[0], W2[1], xp0, xp1,
                          as2[0], as2[1], ad2[0], ad2[1], att2);

    // layer-2 aggregation -> per-relation s partials
    k_agg2<<<dim3(NN, 2), 128>>>(xp0, xp1, att2, offp, srcsp, wlin);

    k_pair<<<NN * NN / 4 / 256, 256>>>(out, blin);
}

// round 11
// speedup vs baseline: 1.2038x; 1.0258x over previous
#include <cuda_runtime.h>
#include <cuda_fp16.h>

#define DEV_INLINE __device__ __forceinline__

constexpr int NN   = 1024;
constexpr int EE   = 65536;
constexpr int E2   = EE + NN;      // edges + self loops
constexpr int W1O  = 512;          // H*256
constexpr int C1   = 256;
constexpr int W2O  = 128;          // H*64
constexpr int C2   = 64;

// ---------------- scratch (device globals) -------------
__device__ __half g_xph[2][NN * W1O];   // layer-1 projected features (fp16)
__device__ float  g_xp[2][NN * W2O];    // layer-2 projected features (fp32)
__device__ float  g_h1a[NN * W1O];      // layer-1 partial (rel 0, normalized)
__device__ float  g_h1b[NN * W1O];      // layer-1 partial (rel 1, normalized)
__device__ float  g_bb[W1O];            // b1_0+b1_1
__device__ float  g_cbias[1];           // sum((b2_0+b2_1)*wlin)
__device__ float  g_att[2][2 * 2 * NN * 2];  // [layer][rel][als/ald][node*2+head]
__device__ int    g_cnt4[4][2][NN];     // sharded edge counts
__device__ int    g_cur4[4][2][NN];     // sharded fill cursors
__device__ int    g_off[2][NN + 1];
__device__ int    g_srcs[2][E2];
__device__ float  g_s2[2][NN];          // per-relation score partials
__device__ int    g_flag;               // scan-done flag

// =======================================================================
// FUSED: gemm1 (both relations, fp16 out) + attn1 logits + sharded count
// =======================================================================
constexpr int G1_GEMM_BLOCKS  = (W1O / 64) * (NN / 128) * 2;   // 128
constexpr int G1_COUNT_BLOCKS = EE / 4 / 256;                  // 64

__global__ void __launch_bounds__(256)
k_gemm1_count(const float* __restrict__ A,
              const float* __restrict__ B0, const float* __restrict__ B1,
              __half* __restrict__ Ch0, __half* __restrict__ Ch1,
              const int* __restrict__ ei0, const int* __restrict__ ei1,
              const float* __restrict__ as0, const float* __restrict__ as1,
              const float* __restrict__ ad0, const float* __restrict__ ad1,
              float* __restrict__ att) {
    int bid = blockIdx.x;
    int t = threadIdx.x;

    if (bid >= G1_GEMM_BLOCKS) {
        if (bid == G1_GEMM_BLOCKS && t == 0) g_flag = 0;   // reset for scanfill
        int cid = bid - G1_GEMM_BLOCKS;
        int idx = cid * 256 + t;
        int4 d0 = ((const int4*)(ei0 + EE))[idx];
        int4 d1 = ((const int4*)(ei1 + EE))[idx];
        atomicAdd(&g_cnt4[0][0][d0.x], 1); atomicAdd(&g_cnt4[1][0][d0.y], 1);
        atomicAdd(&g_cnt4[2][0][d0.z], 1); atomicAdd(&g_cnt4[3][0][d0.w], 1);
        atomicAdd(&g_cnt4[0][1][d1.x], 1); atomicAdd(&g_cnt4[1][1][d1.y], 1);
        atomicAdd(&g_cnt4[2][1][d1.z], 1); atomicAdd(&g_cnt4[3][1][d1.w], 1);
        return;
    }

    constexpr int K = 256, Nc = W1O;
    __shared__ float4 sh[768];
    float*  As  = (float*)sh;
    float4* As4 = sh;                            // row stride 32
    float4* Bs4 = sh + 512;                      // [16][16]

    int rel = bid >> 6;
    int r   = bid & 63;
    int bn  = (r & 7) * 64;
    int bm  = (r >> 3) * 128;
    const float* B = rel ? B1 : B0;
    __half*      Ch = rel ? Ch1 : Ch0;

    int tx = t & 15, ty = t >> 4;
    int am = t >> 2, ak = (t & 3) * 4;

    float4 acc[8];
    #pragma unroll
    for (int i = 0; i < 8; i++) acc[i] = make_float4(0.f, 0.f, 0.f, 0.f);

    float4 a_reg0 = *(const float4*)(A + (size_t)(bm + am) * K + ak);
    float4 a_reg1 = *(const float4*)(A + (size_t)(bm + am + 64) * K + ak);
    float4 b_reg  = *(const float4*)(B + (size_t)(t >> 4) * Nc + bn + (t & 15) * 4);

    for (int k0 = 0; k0 < K; k0 += 16) {
        As[(ak + 0) * 128 + am] = a_reg0.x;
        As[(ak + 1) * 128 + am] = a_reg0.y;
        As[(ak + 2) * 128 + am] = a_reg0.z;
        As[(ak + 3) * 128 + am] = a_reg0.w;
        As[(ak + 0) * 128 + am + 64] = a_reg1.x;
        As[(ak + 1) * 128 + am + 64] = a_reg1.y;
        As[(ak + 2) * 128 + am + 64] = a_reg1.z;
        As[(ak + 3) * 128 + am + 64] = a_reg1.w;
        Bs4[(t >> 4) * 16 + (t & 15)] = b_reg;
        __syncthreads();

        if (k0 + 16 < K) {
            a_reg0 = *(const float4*)(A + (size_t)(bm + am) * K + k0 + 16 + ak);
            a_reg1 = *(const float4*)(A + (size_t)(bm + am + 64) * K + k0 + 16 + ak);
            b_reg  = *(const float4*)(B + (size_t)(k0 + 16 + (t >> 4)) * Nc + bn + (t & 15) * 4);
        }

        #pragma unroll
        for (int k = 0; k < 16; k++) {
            float4 a0 = As4[k * 32 + ty * 2];
            float4 a1 = As4[k * 32 + ty * 2 + 1];
            float4 b  = Bs4[k * 16 + tx];
            float ar[8] = {a0.x, a0.y, a0.z, a0.w, a1.x, a1.y, a1.z, a1.w};
            #pragma unroll
            for (int i = 0; i < 8; i++) {
                acc[i].x = fmaf(ar[i], b.x, acc[i].x);
                acc[i].y = fmaf(ar[i], b.y, acc[i].y);
                acc[i].z = fmaf(ar[i], b.z, acc[i].z);
                acc[i].w = fmaf(ar[i], b.w, acc[i].w);
            }
        }
        __syncthreads();
    }
    #pragma unroll
    for (int i = 0; i < 8; i++) {
        __half2 h01 = __floats2half2_rn(acc[i].x, acc[i].y);
        __half2 h23 = __floats2half2_rn(acc[i].z, acc[i].w);
        uint2 v;
        v.x = *reinterpret_cast<unsigned*>(&h01);
        v.y = *reinterpret_cast<unsigned*>(&h23);
        ((uint2*)(Ch + (size_t)(bm + ty * 8 + i) * Nc))[(bn >> 2) + tx] = v;
    }

    // fused attn1 logit partials
    const float* asrc = rel ? as1 : as0;
    const float* adst = rel ? ad1 : ad0;
    int h   = bn >> 8;
    int cin = (bn & 255) + tx * 4;
    float4 avs = *(const float4*)(asrc + h * C1 + cin);
    float4 avd = *(const float4*)(adst + h * C1 + cin);
    float* alsb = att + (rel * 2 + 0) * (NN * 2);
    float* aldb = att + (rel * 2 + 1) * (NN * 2);
    #pragma unroll
    for (int i = 0; i < 8; i++) {
        float ps = acc[i].x * avs.x + acc[i].y * avs.y + acc[i].z * avs.z + acc[i].w * avs.w;
        float pd = acc[i].x * avd.x + acc[i].y * avd.y + acc[i].z * avd.z + acc[i].w * avd.w;
        #pragma unroll
        for (int o = 8; o; o >>= 1) {
            ps += __shfl_xor_sync(0xffffffffu, ps, o);
            pd += __shfl_xor_sync(0xffffffffu, pd, o);
        }
        if (tx == 0) {
            int row = bm + ty * 8 + i;
            atomicAdd(&alsb[row * 2 + h], ps);
            atomicAdd(&aldb[row * 2 + h], pd);
        }
    }
}

// =======================================================================
// FUSED scan (blocks 0,1) + fill (blocks 2..18), flag-synchronized
// =======================================================================
constexpr int SF_FILL_BLOCKS = 17;   // 16 edge blocks (1024 thr x int4) + 1 self-loop

__global__ void __launch_bounds__(1024)
k_scanfill(const int* __restrict__ ei0, const int* __restrict__ ei1,
           const float* __restrict__ b1_0, const float* __restrict__ b1_1,
           const float* __restrict__ b2_0, const float* __restrict__ b2_1,
           const float* __restrict__ wlin) {
    int b = blockIdx.x;
    int t = threadIdx.x;

    if (b < 2) {
        int r = b;
        __shared__ int sh[NN];
        __shared__ float fred[4];

        int c0 = g_cnt4[0][r][t] + 1;   // self loop in shard 0
        int c1 = g_cnt4[1][r][t];
        int c2 = g_cnt4[2][r][t];
        int c3 = g_cnt4[3][r][t];
        int mine = c0 + c1 + c2 + c3;
        sh[t] = mine;
        __syncthreads();
        #pragma unroll
        for (int d = 1; d < NN; d <<= 1) {
            int v = (t >= d) ? sh[t - d] : 0;
            __syncthreads();
            sh[t] += v;
            __syncthreads();
        }
        g_off[r][t + 1] = sh[t];
        if (t == 0) g_off[r][0] = 0;
        int base = sh[t] - mine;
        g_cur4[0][r][t] = base;
        g_cur4[1][r][t] = base + c0;
        g_cur4[2][r][t] = base + c0 + c1;
        g_cur4[3][r][t] = base + c0 + c1 + c2;

        // side duties
        if (r == 0) {
            if (t < W1O) g_bb[t] = b1_0[t] + b1_1[t];
        } else {
            float p = 0.f;
            if (t < W2O) p = (b2_0[t] + b2_1[t]) * wlin[t];
            if (t < 128) {
                #pragma unroll
                for (int o = 16; o; o >>= 1) p += __shfl_xor_sync(0xffffffffu, p, o);
                if ((t & 31) == 0) fred[t >> 5] = p;
            }
            __syncthreads();
            if (t == 0) g_cbias[0] = fred[0] + fred[1] + fred[2] + fred[3];
        }

        __threadfence();
        __syncthreads();
        if (t == 0) atomicAdd(&g_flag, 1);
        return;
    }

    // ---- fill blocks: wait for both scan blocks ----
    if (t == 0) {
        while (atomicAdd(&g_flag, 0) < 2) {}
    }
    __syncthreads();
    __threadfence();

    int fb = b - 2;
    if (fb < 16) {
        int idx = fb * 1024 + t;     // int4 index; 16*1024 = EE/4
        int4 s0 = ((const int4*)ei0)[idx];
        int4 d0 = ((const int4*)(ei0 + EE))[idx];
        int4 s1 = ((const int4*)ei1)[idx];
        int4 d1 = ((const int4*)(ei1 + EE))[idx];
        int p;
        p = atomicAdd(&g_cur4[0][0][d0.x], 1); g_srcs[0][p] = s0.x;
        p = atomicAdd(&g_cur4[1][0][d0.y], 1); g_srcs[0][p] = s0.y;
        p = atomicAdd(&g_cur4[2][0][d0.z], 1); g_srcs[0][p] = s0.z;
        p = atomicAdd(&g_cur4[3][0][d0.w], 1); g_srcs[0][p] = s0.w;
        p = atomicAdd(&g_cur4[0][1][d1.x], 1); g_srcs[1][p] = s1.x;
        p = atomicAdd(&g_cur4[1][1][d1.y], 1); g_srcs[1][p] = s1.y;
        p = atomicAdd(&g_cur4[2][1][d1.z], 1); g_srcs[1][p] = s1.z;
        p = atomicAdd(&g_cur4[3][1][d1.w], 1); g_srcs[1][p] = s1.w;
    } else {
        int n = t;   // self loops
        int p0 = atomicAdd(&g_cur4[0][0][n], 1); g_srcs[0][p0] = n;
        int p1 = atomicAdd(&g_cur4[0][1][n], 1); g_srcs[1][p1] = n;
    }
}

// =======================================================================
// agg1: block per (dst, rel); fp16 gather; writes NORMALIZED partial
// =======================================================================
__global__ void __launch_bounds__(128)
k_agg1(const __half* __restrict__ xp0, const __half* __restrict__ xp1,
       const float* __restrict__ att,
       const int* __restrict__ off, const int* __restrict__ srcs,
       float* __restrict__ h1a, float* __restrict__ h1b) {
    constexpr int CH = 512;
    __shared__ int   sh_src[CH];
    __shared__ float sh_e[2][CH];
    __shared__ float red[8];

    int dst = blockIdx.x, rel = blockIdx.y, t = threadIdx.x;
    const __half* xp    = rel ? xp1 : xp0;
    float*        outp  = rel ? h1b : h1a;
    const float*  alsr  = att + (rel * 2 + 0) * (NN * 2);
    const float*  aldr  = att + (rel * 2 + 1) * (NN * 2);
    const int*    offr  = off + (size_t)rel * (NN + 1);
    const int*    srcsr = srcs + (size_t)rel * E2;

    int head = ((t * 4) >= C1) ? 1 : 0;
    int o0 = offr[dst];
    int range = offr[dst + 1] - o0;
    float ad0 = aldr[dst * 2 + 0], ad1 = aldr[dst * 2 + 1];

    float sum0 = 0.f, sum1 = 0.f;
    float4 a4 = make_float4(0.f, 0.f, 0.f, 0.f);

    for (int base = 0; base < range; base += CH) {
        int nn = min(CH, range - base);
        __syncthreads();
        for (int i = t; i < nn; i += 128) {
            int s = srcsr[o0 + base + i];
            sh_src[i] = s;
            float l0 = alsr[s * 2 + 0] + ad0; l0 = l0 > 0.f ? l0 : 0.2f * l0;
            float l1 = alsr[s * 2 + 1] + ad1; l1 = l1 > 0.f ? l1 : 0.2f * l1;
            float e0 = expf(l0);
            float e1 = expf(l1);
            sh_e[0][i] = e0; sh_e[1][i] = e1;
            sum0 += e0; sum1 += e1;
        }
        __syncthreads();
        const float* eh = sh_e[head];
        #pragma unroll 4
        for (int j = 0; j < nn; j++) {
            int s = sh_src[j];
            float e = eh[j];
            uint2 v = ((const uint2*)(xp + (size_t)s * W1O))[t];
            __half2 h01 = *reinterpret_cast<__half2*>(&v.x);
            __half2 h23 = *reinterpret_cast<__half2*>(&v.y);
            float2 f01 = __half22float2(h01);
            float2 f23 = __half22float2(h23);
            a4.x = fmaf(e, f01.x, a4.x);
            a4.y = fmaf(e, f01.y, a4.y);
            a4.z = fmaf(e, f23.x, a4.z);
            a4.w = fmaf(e, f23.y, a4.w);
        }
    }
    #pragma unroll
    for (int o = 16; o; o >>= 1) {
        sum0 += __shfl_xor_sync(0xffffffffu, sum0, o);
        sum1 += __shfl_xor_sync(0xffffffffu, sum1, o);
    }
    if ((t & 31) == 0) { red[t >> 5] = sum0; red[4 + (t >> 5)] = sum1; }
    __syncthreads();
    sum0 = red[0] + red[1] + red[2] + red[3];
    sum1 = red[4] + red[5] + red[6] + red[7];
    float inv = head ? 1.f / (sum1 + 1e-16f) : 1.f / (sum0 + 1e-16f);
    float4 v;
    v.x = a4.x * inv; v.y = a4.y * inv; v.z = a4.z * inv; v.w = a4.w * inv;
    ((float4*)(outp + (size_t)dst * W1O))[t] = v;
}

// =======================================================================
// gemm2: split-K=2 (blockIdx.y), 256 threads, 2x4 micro-tile.
// A = relu(h1a + h1b + bb) on the fly. Atomic-accumulate C (pre-zeroed)
// and attn2 logit partials (both linear in the accumulator).
// =======================================================================
DEV_INLINE float4 ld_h1(const float* __restrict__ h1a, const float* __restrict__ h1b,
                        size_t row, int k) {
    float4 a = *(const float4*)(h1a + row * W1O + k);
    float4 b = *(const float4*)(h1b + row * W1O + k);
    float4 c = *(const float4*)(g_bb + k);
    float4 v;
    v.x = a.x + b.x + c.x; v.x = v.x > 0.f ? v.x : 0.f;
    v.y = a.y + b.y + c.y; v.y = v.y > 0.f ? v.y : 0.f;
    v.z = a.z + b.z + c.z; v.z = v.z > 0.f ? v.z : 0.f;
    v.w = a.w + b.w + c.w; v.w = v.w > 0.f ? v.w : 0.f;
    return v;
}

__global__ void __launch_bounds__(256)
k_gemm2(const float* __restrict__ h1a, const float* __restrict__ h1b,
        const float* __restrict__ B0, const float* __restrict__ B1,
        float* __restrict__ Co0, float* __restrict__ Co1,
        const float* __restrict__ as0, const float* __restrict__ as1,
        const float* __restrict__ ad0, const float* __restrict__ ad1,
        float* __restrict__ att) {
    constexpr int Nc = W2O;
    constexpr int KH = 256;                      // K half
    __shared__ float smem[16 * 64 + 16 * 32];    // As [16][64] + Bs [16][32]
    float* As = smem;
    float* Bs = smem + 16 * 64;

    int bid = blockIdx.x;
    int kb  = blockIdx.y * KH;                   // K-half base
    int rel = bid >> 6;
    int r   = bid & 63;
    int bn  = (r & 3) * 32;
    int bm  = (r >> 2) * 64;
    const float* B = rel ? B1 : B0;
    float*       C = rel ? Co1 : Co0;

    int t = threadIdx.x;
    int tx = t & 7, ty = t >> 3;                 // 8 x 32
    int am = t >> 2, ak = (t & 3) * 4;           // A load: float4 per thread
    int brow = t >> 4, bcol = (t & 15) * 2;      // B load: float2 per thread

    float4 acc[2];
    acc[0] = make_float4(0.f, 0.f, 0.f, 0.f);
    acc[1] = make_float4(0.f, 0.f, 0.f, 0.f);

    float4 a_reg = ld_h1(h1a, h1b, (size_t)(bm + am), kb + ak);
    float2 b_reg = *(const float2*)(B + (size_t)(kb + brow) * Nc + bn + bcol);

    for (int k0 = 0; k0 < KH; k0 += 16) {
        As[(ak + 0) * 64 + am] = a_reg.x;
        As[(ak + 1) * 64 + am] = a_reg.y;
        As[(ak + 2) * 64 + am] = a_reg.z;
        As[(ak + 3) * 64 + am] = a_reg.w;
        Bs[brow * 32 + bcol + 0] = b_reg.x;
        Bs[brow * 32 + bcol + 1] = b_reg.y;
        __syncthreads();

        if (k0 + 16 < KH) {
            a_reg = ld_h1(h1a, h1b, (size_t)(bm + am), kb + k0 + 16 + ak);
            b_reg = *(const float2*)(B + (size_t)(kb + k0 + 16 + brow) * Nc + bn + bcol);
        }

        #pragma unroll
        for (int k = 0; k < 16; k++) {
            float2 a = ((const float2*)(As + k * 64))[ty];
            float4 b = ((const float4*)(Bs + k * 32))[tx];
            acc[0].x = fmaf(a.x, b.x, acc[0].x);
            acc[0].y = fmaf(a.x, b.y, acc[0].y);
            acc[0].z = fmaf(a.x, b.z, acc[0].z);
            acc[0].w = fmaf(a.x, b.w, acc[0].w);
            acc[1].x = fmaf(a.y, b.x, acc[1].x);
            acc[1].y = fmaf(a.y, b.y, acc[1].y);
            acc[1].z = fmaf(a.y, b.z, acc[1].z);
            acc[1].w = fmaf(a.y, b.w, acc[1].w);
        }
        __syncthreads();
    }

    // atomic-accumulate C (pre-zeroed)
    #pragma unroll
    for (int i = 0; i < 2; i++) {
        float* cp = C + (size_t)(bm + ty * 2 + i) * Nc + bn + tx * 4;
        atomicAdd(cp + 0, acc[i].x);
        atomicAdd(cp + 1, acc[i].y);
        atomicAdd(cp + 2, acc[i].z);
        atomicAdd(cp + 3, acc[i].w);
    }

    // fused attn2 logit partials (linear in acc -> valid per K-half)
    const float* asrc = rel ? as1 : as0;
    const float* adst = rel ? ad1 : ad0;
    int h   = bn >> 6;
    int cin = (bn & 63) + tx * 4;
    float4 avs = *(const float4*)(asrc + h * C2 + cin);
    float4 avd = *(const float4*)(adst + h * C2 + cin);
    float* alsb = att + (rel * 2 + 0) * (NN * 2);
    float* aldb = att + (rel * 2 + 1) * (NN * 2);
    #pragma unroll
    for (int i = 0; i < 2; i++) {
        float ps = acc[i].x * avs.x + acc[i].y * avs.y + acc[i].z * avs.z + acc[i].w * avs.w;
        float pd = acc[i].x * avd.x + acc[i].y * avd.y + acc[i].z * avd.z + acc[i].w * avd.w;
        #pragma unroll
        for (int o = 4; o; o >>= 1) {
            ps += __shfl_xor_sync(0xffffffffu, ps, o);
            pd += __shfl_xor_sync(0xffffffffu, pd, o);
        }
        if (tx == 0) {
            int row = bm + ty * 2 + i;
            atomicAdd(&alsb[row * 2 + h], ps);
            atomicAdd(&aldb[row * 2 + h], pd);
        }
    }
}

// =======================================================================
// agg2: block per (dst, rel); plain-store per-relation partial s
// =======================================================================
__global__ void __launch_bounds__(128)
k_agg2(const float* __restrict__ xp0, const float* __restrict__ xp1,
       const float* __restrict__ att,
       const int* __restrict__ off, const int* __restrict__ srcs,
       const float* __restrict__ wlin) {
    constexpr int CH = 512;
    __shared__ int   sh_src[CH];
    __shared__ float sh_e[2][CH];
    __shared__ float red[8];

    int dst = blockIdx.x, rel = blockIdx.y, t = threadIdx.x;
    const float* xp    = rel ? xp1 : xp0;
    const float* alsr  = att + (rel * 2 + 0) * (NN * 2);
    const float* aldr  = att + (rel * 2 + 1) * (NN * 2);
    const int*   offr  = off + (size_t)rel * (NN + 1);
    const int*   srcsr = srcs + (size_t)rel * E2;

    int head = (t >= C2) ? 1 : 0;
    int o0 = offr[dst];
    int range = offr[dst + 1] - o0;
    float ad0 = aldr[dst * 2 + 0], ad1 = aldr[dst * 2 + 1];

    float sum0 = 0.f, sum1 = 0.f;
    float a1 = 0.f;

    for (int base = 0; base < range; base += CH) {
        int nn = min(CH, range - base);
        __syncthreads();
        for (int i = t; i < nn; i += 128) {
            int s = srcsr[o0 + base + i];
            sh_src[i] = s;
            float l0 = alsr[s * 2 + 0] + ad0; l0 = l0 > 0.f ? l0 : 0.2f * l0;
            float l1 = alsr[s * 2 + 1] + ad1; l1 = l1 > 0.f ? l1 : 0.2f * l1;
            float e0 = expf(l0);
            float e1 = expf(l1);
            sh_e[0][i] = e0; sh_e[1][i] = e1;
            sum0 += e0; sum1 += e1;
        }
        __syncthreads();
        const float* eh = sh_e[head];
        #pragma unroll 4
        for (int j = 0; j < nn; j++) {
            int s = sh_src[j];
            a1 = fmaf(eh[j], xp[(size_t)s * W2O + t], a1);
        }
    }
    #pragma unroll
    for (int o = 16; o; o >>= 1) {
        sum0 += __shfl_xor_sync(0xffffffffu, sum0, o);
        sum1 += __shfl_xor_sync(0xffffffffu, sum1, o);
    }
    if ((t & 31) == 0) { red[t >> 5] = sum0; red[4 + (t >> 5)] = sum1; }
    __syncthreads();
    sum0 = red[0] + red[1] + red[2] + red[3];
    sum1 = red[4] + red[5] + red[6] + red[7];
    float inv = head ? 1.f / (sum1 + 1e-16f) : 1.f / (sum0 + 1e-16f);
    float p = a1 * inv * wlin[t];
    #pragma unroll
    for (int o = 16; o; o >>= 1) p += __shfl_xor_sync(0xffffffffu, p, o);
    __syncthreads();
    if ((t & 31) == 0) red[t >> 5] = p;
    __syncthreads();
    if (t == 0) g_s2[rel][dst] = red[0] + red[1] + red[2] + red[3];
}

// ---------------- pairwise output: out[i*N+j] = s[i]+s[j]+2*cbias+b -------
__global__ void k_pair(float* __restrict__ out, const float* __restrict__ blin) {
    int idx = blockIdx.x * blockDim.x + threadIdx.x;
    float b = blin[0] + 2.f * g_cbias[0];
    int i = idx >> 8;
    int j4 = (idx & 255) << 2;
    float si = g_s2[0][i] + g_s2[1][i] + b;
    float4 v;
    v.x = si + g_s2[0][j4 + 0] + g_s2[1][j4 + 0];
    v.y = si + g_s2[0][j4 + 1] + g_s2[1][j4 + 1];
    v.z = si + g_s2[0][j4 + 2] + g_s2[1][j4 + 2];
    v.w = si + g_s2[0][j4 + 3] + g_s2[1][j4 + 3];
    ((float4*)out)[idx] = v;
}

// ---------------- launch ----------------
extern "C" void kernel_launch(void* const* d_in, const int* in_sizes, int n_in,
                              void* d_out, int out_size) {
    const float* x    = (const float*)d_in[0];
    const int*   ei0  = (const int*)d_in[1];
    const int*   ei1  = (const int*)d_in[2];
    const float* W1[2]  = {(const float*)d_in[3],  (const float*)d_in[7]};
    const float* as1[2] = {(const float*)d_in[4],  (const float*)d_in[8]};
    const float* ad1[2] = {(const float*)d_in[5],  (const float*)d_in[9]};
    const float* b1[2]  = {(const float*)d_in[6],  (const float*)d_in[10]};
    const float* W2[2]  = {(const float*)d_in[11], (const float*)d_in[15]};
    const float* as2[2] = {(const float*)d_in[12], (const float*)d_in[16]};
    const float* ad2[2] = {(const float*)d_in[13], (const float*)d_in[17]};
    const float* b2[2]  = {(const float*)d_in[14], (const float*)d_in[18]};
    const float* wlin = (const float*)d_in[19];
    const float* blin = (const float*)d_in[20];
    float* out = (float*)d_out;

    float *xp, *h1a, *h1b, *attp;
    __half* xph;
    int *cnt4p, *offp, *srcsp;
    cudaGetSymbolAddress((void**)&xph,   g_xph);
    cudaGetSymbolAddress((void**)&xp,    g_xp);
    cudaGetSymbolAddress((void**)&h1a,   g_h1a);
    cudaGetSymbolAddress((void**)&h1b,   g_h1b);
    cudaGetSymbolAddress((void**)&attp,  g_att);
    cudaGetSymbolAddress((void**)&cnt4p, g_cnt4);
    cudaGetSymbolAddress((void**)&offp,  g_off);
    cudaGetSymbolAddress((void**)&srcsp, g_srcs);

    __half* xph0 = xph;
    __half* xph1 = xph + (size_t)NN * W1O;
    float*  xp0  = xp;
    float*  xp1  = xp + (size_t)NN * W2O;
    float*  att1 = attp;
    float*  att2 = attp + (2 * 2 * NN * 2);

    cudaMemsetAsync(cnt4p, 0, 4 * 2 * NN * sizeof(int));
    cudaMemsetAsync(attp, 0, 2 * (2 * 2 * NN * 2) * sizeof(float));
    cudaMemsetAsync(xp, 0, 2 * NN * W2O * sizeof(float));   // split-K accumulator

    // gemm1 (fp16 out, +attn1 epilogue) + sharded count
    k_gemm1_count<<<G1_GEMM_BLOCKS + G1_COUNT_BLOCKS, 256>>>(
        x, W1[0], W1[1], xph0, xph1, ei0, ei1,
        as1[0], as1[1], ad1[0], ad1[1], att1);

    // fused scan + fill
    k_scanfill<<<2 + SF_FILL_BLOCKS, 1024>>>(
        ei0, ei1, b1[0], b1[1], b2[0], b2[1], wlin);

    // layer-1 aggregation
    k_agg1<<<dim3(NN, 2), 128>>>(xph0, xph1, att1, offp, srcsp, h1a, h1b);

    // gemm2: split-K=2, 256 threads, atomic accumulate
    k_gemm2<<<dim3(128, 2), 256>>>(h1a, h1b, W2[0], W2[1], xp0, xp1,
                                   as2[0], as2[1], ad2[0], ad2[1], att2);

    // layer-2 aggregation -> per-relation s partials
    k_agg2<<<dim3(NN, 2), 128>>>(xp0, xp1, att2, offp, srcsp, wlin);

    k_pair<<<NN * NN / 4 / 256, 256>>>(out, blin);
}